// round 5
// baseline (speedup 1.0000x reference)
#include <cuda_runtime.h>
#include <stdint.h>

#define D1    256
#define D2    256
#define ODIM  1024
#define BB    64
#define SS    128
#define KTOT  (D1 * D2)       // 65536

// ---------------- stage-2 mma.sync GEMM config ----------------
#define KS2   16              // k-split CTAs (grid.y)
#define KSL   (KS2 * 2)       // total partial slices (2 warp-groups per CTA)
#define NT2   128             // n-tile (output cols per CTA)
#define KC2   32              // k per pipeline stage
#define STG   6               // pipeline depth
#define PRE   5               // prefetch distance (< STG)
#define KPER2 (KTOT / KS2)    // 4096
#define NIT   (KPER2 / KC2)   // 128 stages

#define PITCH        36                          // floats per smem row (32 data + 4 pad)
#define A_FLOATS     (64  * PITCH)               // 2304
#define B_FLOATS     (NT2 * PITCH)               // 4608
#define STAGE_FLOATS (A_FLOATS + B_FLOATS)       // 6912
#define SMEM_DYN     (STG * STAGE_FLOATS * 4)    // 165888 B

// Device-global scratch (allocation-free per harness rules)
__device__ float g_tp[(size_t)BB * KTOT];                 // tp[b][k] (tf32-rounded)
__device__ float g_partial[(size_t)KSL * BB * ODIM];      // 8 MB

// ---------------------------------------------------------------------------
// helpers
// ---------------------------------------------------------------------------
__device__ __forceinline__ uint32_t smem_u32(const void* p) {
    uint32_t a;
    asm("{ .reg .u64 t; cvta.to.shared.u64 t, %1; cvt.u32.u64 %0, t; }" : "=r"(a) : "l"(p));
    return a;
}
__device__ __forceinline__ void fma2(unsigned long long& acc,
                                     unsigned long long a, unsigned long long w) {
    asm("fma.rn.f32x2 %0, %1, %2, %0;" : "+l"(acc) : "l"(a), "l"(w));
}
__device__ __forceinline__ unsigned long long round_tf32x2(unsigned long long v) {
    float2 f = *(float2*)&v;
    uint32_t lo, hi;
    asm("cvt.rna.tf32.f32 %0, %1;" : "=r"(lo) : "f"(f.x));
    asm("cvt.rna.tf32.f32 %0, %1;" : "=r"(hi) : "f"(f.y));
    return (unsigned long long)lo | ((unsigned long long)hi << 32);
}
__device__ __forceinline__ uint32_t to_tf32(float f) {
    uint32_t r;
    asm("cvt.rna.tf32.f32 %0, %1;" : "=r"(r) : "f"(f));
    return r;
}
__device__ __forceinline__ void cp16(uint32_t dst, const void* src) {
    asm volatile("cp.async.cg.shared.global [%0], [%1], 16;" :: "r"(dst), "l"(src));
}
// m16n8k8 tf32: A row-major (4 regs), B col-major (2 regs), C fp32 (4 regs)
__device__ __forceinline__ void mma_tf32(float* c, const uint32_t* a, const uint32_t* b) {
    asm volatile(
        "mma.sync.aligned.m16n8k8.row.col.f32.tf32.tf32.f32 "
        "{%0,%1,%2,%3}, {%4,%5,%6,%7}, {%8,%9}, {%0,%1,%2,%3};"
        : "+f"(c[0]), "+f"(c[1]), "+f"(c[2]), "+f"(c[3])
        : "r"(a[0]), "r"(a[1]), "r"(a[2]), "r"(a[3]), "r"(b[0]), "r"(b[1]));
}

// ---------------------------------------------------------------------------
// Stage 1: tp[b, d, e] = sum_s F[fillers[b,s], d] * R[roles[b,s], e]
// grid (e-tiles=4, b=64, d-halves=2), 256 thr. Output rounded to tf32.
// Register-prefetch of next chunk's gather overlaps it with compute.
// ---------------------------------------------------------------------------
__global__ __launch_bounds__(256) void tp_kernel(
    const int*   __restrict__ fillers,
    const int*   __restrict__ roles,
    const float* __restrict__ ftab,
    const float* __restrict__ rtab)
{
    const int b   = blockIdx.y;
    const int e0  = blockIdx.x * 64;
    const int d0  = blockIdx.z * 128;
    const int tid = threadIdx.x;

    __shared__ int    s_fi[SS];
    __shared__ int    s_ri[SS];
    __shared__ float2 sF[16][128];   // duplicated filler embeddings (16 KB)
    __shared__ float  sR[16][64];    // role e-tile (4 KB)

    if (tid < SS)          s_fi[tid]      = fillers[b * SS + tid];
    else if (tid < 2 * SS) s_ri[tid - SS] = roles[b * SS + (tid - SS)];
    __syncthreads();

    const int te  = tid & 7;
    const int tdd = tid >> 3;
    const int s_l  = tid >> 4;          // staging row 0..15
    const int dseg = (tid & 15) * 8;    // staging d segment
    const int e4   = (tid & 15) * 4;    // staging e segment

    unsigned long long acc[4][4];
    #pragma unroll
    for (int i = 0; i < 4; i++)
        #pragma unroll
        for (int j = 0; j < 4; j++) acc[i][j] = 0ull;

    // prefetch registers
    float4 pf0, pf1, pr;
    {
        const float* row = ftab + (size_t)s_fi[s_l] * D1 + d0 + dseg;
        pf0 = ((const float4*)row)[0];
        pf1 = ((const float4*)row)[1];
        pr  = *(const float4*)(rtab + (size_t)s_ri[s_l] * D2 + e0 + e4);
    }

    for (int sc = 0; sc < SS; sc += 16) {
        __syncthreads();
        // store prefetched chunk to smem
        sF[s_l][dseg + 0] = make_float2(pf0.x, pf0.x);
        sF[s_l][dseg + 1] = make_float2(pf0.y, pf0.y);
        sF[s_l][dseg + 2] = make_float2(pf0.z, pf0.z);
        sF[s_l][dseg + 3] = make_float2(pf0.w, pf0.w);
        sF[s_l][dseg + 4] = make_float2(pf1.x, pf1.x);
        sF[s_l][dseg + 5] = make_float2(pf1.y, pf1.y);
        sF[s_l][dseg + 6] = make_float2(pf1.z, pf1.z);
        sF[s_l][dseg + 7] = make_float2(pf1.w, pf1.w);
        sR[s_l][e4 + 0] = pr.x; sR[s_l][e4 + 1] = pr.y;
        sR[s_l][e4 + 2] = pr.z; sR[s_l][e4 + 3] = pr.w;
        __syncthreads();

        // issue next chunk's gather; latency overlaps the compute below
        if (sc + 16 < SS) {
            const float* row = ftab + (size_t)s_fi[sc + 16 + s_l] * D1 + d0 + dseg;
            pf0 = ((const float4*)row)[0];
            pf1 = ((const float4*)row)[1];
            pr  = *(const float4*)(rtab + (size_t)s_ri[sc + 16 + s_l] * D2 + e0 + e4);
        }

        #pragma unroll
        for (int s = 0; s < 16; s++) {
            unsigned long long a[4], w[4];
            #pragma unroll
            for (int i = 0; i < 4; i++)
                a[i] = *(const unsigned long long*)&sF[s][tdd + 32 * i];
            #pragma unroll
            for (int j = 0; j < 4; j++)
                w[j] = *(const unsigned long long*)&sR[s][te * 2 + 16 * j];
            #pragma unroll
            for (int i = 0; i < 4; i++)
                #pragma unroll
                for (int j = 0; j < 4; j++)
                    fma2(acc[i][j], a[i], w[j]);
        }
    }

    float* tpb = g_tp + (size_t)b * KTOT;
    #pragma unroll
    for (int i = 0; i < 4; i++) {
        const int d = d0 + tdd + 32 * i;
        #pragma unroll
        for (int j = 0; j < 4; j++) {
            const int e = e0 + te * 2 + 16 * j;
            *(unsigned long long*)(tpb + (size_t)d * D2 + e) = round_tf32x2(acc[i][j]);
        }
    }
}

// ---------------------------------------------------------------------------
// Stage 2: mma.sync tf32 GEMM.  partial slices: sum_{k in split} tp[b,k]*W[o,k]
// grid (8 n-tiles, 16 k-splits), 256 thr (8 warps), 1 CTA/SM.
// Warp-groups split the stage's k-range (2 SMSP-resident warps each) and
// accumulate into separate partial slices (ks*2 + kq).
// ---------------------------------------------------------------------------
__global__ __launch_bounds__(256, 1) void gemm2_mma(const float* __restrict__ Wm)
{
    extern __shared__ float dsm[];

    const int tid  = threadIdx.x;
    const int wid  = tid >> 5;
    const int lane = tid & 31;
    const int o0   = blockIdx.x * NT2;
    const int ks   = blockIdx.y;
    const size_t k_base = (size_t)ks * KPER2;

    const int g  = lane >> 2;      // group id 0..7
    const int t  = lane & 3;       // thread-in-group
    const int n0 = (wid & 3) * 32; // warp's n offset within tile
    const int kq = wid >> 2;       // 0/1: which half of the stage's k

    // staging mapping (256 threads, 6 cp16 each)
    const int c8    = tid & 7;
    const int rbase = tid >> 3;    // 0..31

    const uint32_t smem_base = smem_u32(dsm);

    float acc[4][4][4];
    #pragma unroll
    for (int i = 0; i < 4; i++)
        #pragma unroll
        for (int j = 0; j < 4; j++)
            #pragma unroll
            for (int q = 0; q < 4; q++) acc[i][j][q] = 0.f;

    auto load_stage = [&](int j) {
        if (j < NIT) {
            const uint32_t sbase = smem_base + (uint32_t)(j % STG) * (STAGE_FLOATS * 4);
            const size_t kf = k_base + (size_t)j * KC2 + c8 * 4;
            #pragma unroll
            for (int p = 0; p < 2; p++) {            // A: tp rows 0..63
                const int row = rbase + 32 * p;
                cp16(sbase + (uint32_t)(row * PITCH + c8 * 4) * 4,
                     g_tp + (size_t)row * KTOT + kf);
            }
            #pragma unroll
            for (int p = 0; p < 4; p++) {            // B: W rows 0..127
                const int row = rbase + 32 * p;
                cp16(sbase + (uint32_t)(A_FLOATS + row * PITCH + c8 * 4) * 4,
                     Wm + (size_t)(o0 + row) * KTOT + kf);
            }
        }
        asm volatile("cp.async.commit_group;" ::: "memory");
    };

    #pragma unroll
    for (int j = 0; j < PRE; j++) load_stage(j);

    for (int it = 0; it < NIT; it++) {
        asm volatile("cp.async.wait_group 4;" ::: "memory");   // PRE-1
        __syncthreads();

        load_stage(it + PRE);

        const float* sA = dsm + (it % STG) * STAGE_FLOATS;
        const float* sB = sA + A_FLOATS;

        #pragma unroll
        for (int qi = 0; qi < 2; qi++) {
            const int k0 = (kq * 2 + qi) * 8;
            uint32_t a[4][4];
            #pragma unroll
            for (int i = 0; i < 4; i++) {
                const int m = i * 16 + g;
                a[i][0] = __float_as_uint(sA[m       * PITCH + k0 + t]);
                a[i][1] = __float_as_uint(sA[(m + 8) * PITCH + k0 + t]);
                a[i][2] = __float_as_uint(sA[m       * PITCH + k0 + t + 4]);
                a[i][3] = __float_as_uint(sA[(m + 8) * PITCH + k0 + t + 4]);
            }
            uint32_t b[4][2];
            #pragma unroll
            for (int j = 0; j < 4; j++) {
                const int n = n0 + j * 8 + g;
                b[j][0] = to_tf32(sB[n * PITCH + k0 + t]);
                b[j][1] = to_tf32(sB[n * PITCH + k0 + t + 4]);
            }
            #pragma unroll
            for (int i = 0; i < 4; i++)
                #pragma unroll
                for (int j = 0; j < 4; j++)
                    mma_tf32(acc[i][j], a[i], b[j]);
        }
    }

    // epilogue: write this warp-group's partial slice
    float* part = g_partial + (size_t)(ks * 2 + kq) * (BB * ODIM);
    #pragma unroll
    for (int i = 0; i < 4; i++) {
        const int b_row = i * 16 + g;
        #pragma unroll
        for (int j = 0; j < 4; j++) {
            const int col = o0 + n0 + j * 8 + 2 * t;
            *(float2*)(part + (size_t)b_row * ODIM + col) =
                make_float2(acc[i][j][0], acc[i][j][1]);
            *(float2*)(part + (size_t)(b_row + 8) * ODIM + col) =
                make_float2(acc[i][j][2], acc[i][j][3]);
        }
    }
}

// ---------------------------------------------------------------------------
// Reduce: out[b][o] = bias[o] + sum_slices partial[sl][b][o]
// ---------------------------------------------------------------------------
__global__ __launch_bounds__(256) void reduce_kernel(
    const float* __restrict__ bias, float* __restrict__ out)
{
    const int idx = blockIdx.x * blockDim.x + threadIdx.x;
    const int o4  = (idx * 4) & (ODIM - 1);
    const int b   = (idx * 4) >> 10;

    float4 acc = *(const float4*)(bias + o4);
    const float* p = g_partial + (size_t)b * ODIM + o4;
    #pragma unroll
    for (int sl = 0; sl < KSL; sl++) {
        float4 v = *(const float4*)(p + (size_t)sl * (BB * ODIM));
        acc.x += v.x; acc.y += v.y; acc.z += v.z; acc.w += v.w;
    }
    *(float4*)(out + (size_t)b * ODIM + o4) = acc;
}

// ---------------------------------------------------------------------------
extern "C" void kernel_launch(void* const* d_in, const int* in_sizes, int n_in,
                              void* d_out, int out_size)
{
    const int*   fillers = (const int*)  d_in[0];
    const int*   roles   = (const int*)  d_in[1];
    const float* ftab    = (const float*)d_in[2];
    const float* rtab    = (const float*)d_in[3];
    const float* Wm      = (const float*)d_in[4];
    const float* bias    = (const float*)d_in[5];
    float* out = (float*)d_out;

    cudaFuncSetAttribute(gemm2_mma, cudaFuncAttributeMaxDynamicSharedMemorySize, SMEM_DYN);

    tp_kernel    <<<dim3(D2 / 64, BB, 2), 256>>>(fillers, roles, ftab, rtab);
    gemm2_mma    <<<dim3(ODIM / NT2, KS2), 256, SMEM_DYN>>>(Wm);
    reduce_kernel<<<(BB * ODIM / 4) / 256, 256>>>(bias, out);
}

// round 6
// speedup vs baseline: 1.5578x; 1.5578x over previous
#include <cuda_runtime.h>
#include <cuda_fp16.h>
#include <stdint.h>

#define D1    256
#define D2    256
#define ODIM  1024
#define BB    64
#define SS    128
#define KTOT  (D1 * D2)       // 65536

// ---------------- stage-1 (tp) mma config ----------------
#define PW1   68                       // words per smem row (136 f16 = 272 B)
#define SA1_WORDS (D1 * PW1)           // A: 256 rows
#define SB1_WORDS (128 * PW1)          // B: 128 e rows
#define SMEM1 ((SA1_WORDS + SB1_WORDS) * 4)   // 104448 B

// ---------------- stage-2 mma config ----------------
#define KS2   16              // k-split CTAs
#define NT2   128             // n-tile
#define KC2   32              // k per stage
#define STG   6
#define PRE   5
#define KPER2 (KTOT / KS2)    // 4096
#define NIT   (KPER2 / KC2)   // 128

#define A2_BYTES  (64 * 80)            // A: 64 rows x (32 f16 + pad) = 5120
#define B2_BYTES  (128 * 144)          // B: 128 rows x (32 f32 + pad) = 18432
#define STAGE_B   (A2_BYTES + B2_BYTES)
#define SMEM2     (STG * STAGE_B)      // 141312

// Device-global scratch
__device__ __half g_tp[(size_t)BB * KTOT];            // fp16 tp
__device__ float  g_partial[(size_t)KS2 * BB * ODIM];

// ---------------------------------------------------------------------------
// helpers
// ---------------------------------------------------------------------------
__device__ __forceinline__ uint32_t smem_u32(const void* p) {
    uint32_t a;
    asm("{ .reg .u64 t; cvta.to.shared.u64 t, %1; cvt.u32.u64 %0, t; }" : "=r"(a) : "l"(p));
    return a;
}
__device__ __forceinline__ uint32_t pack_h2(float lo, float hi) {
    uint32_t r;
    asm("cvt.rn.f16x2.f32 %0, %1, %2;" : "=r"(r) : "f"(hi), "f"(lo));  // first src -> hi
    return r;
}
__device__ __forceinline__ void cp16(uint32_t dst, const void* src) {
    asm volatile("cp.async.cg.shared.global [%0], [%1], 16;" :: "r"(dst), "l"(src));
}
// m16n8k16 fp16: A 4 regs, B 2 regs, C fp32 4 regs
__device__ __forceinline__ void hmma(float* c, const uint32_t* a, const uint32_t* b) {
    asm volatile(
        "mma.sync.aligned.m16n8k16.row.col.f32.f16.f16.f32 "
        "{%0,%1,%2,%3}, {%4,%5,%6,%7}, {%8,%9}, {%0,%1,%2,%3};"
        : "+f"(c[0]), "+f"(c[1]), "+f"(c[2]), "+f"(c[3])
        : "r"(a[0]), "r"(a[1]), "r"(a[2]), "r"(a[3]), "r"(b[0]), "r"(b[1]));
}

// ---------------------------------------------------------------------------
// Stage 1: tp[b, d, e] = sum_s F[fillers[b,s], d] * R[roles[b,s], e]  (fp16 MMA)
// grid (e-half=2, b=64), 256 thr (8 warps). Warp tile 64d x 64e, k = s = 128.
// smem: sA[d][s] f16 pitch 68 words, sB[e][s] f16 pitch 68 — transposed gather.
// ---------------------------------------------------------------------------
__global__ __launch_bounds__(256, 1) void tp_mma(
    const int*   __restrict__ fillers,
    const int*   __restrict__ roles,
    const float* __restrict__ ftab,
    const float* __restrict__ rtab)
{
    extern __shared__ uint32_t sm1[];
    uint32_t* sAw = sm1;                 // [256][68] words
    uint32_t* sBw = sm1 + SA1_WORDS;     // [128][68] words

    __shared__ int s_fi[SS];
    __shared__ int s_ri[SS];

    const int b   = blockIdx.y;
    const int e0  = blockIdx.x * 128;
    const int tid = threadIdx.x;
    const int wid  = tid >> 5;
    const int lane = tid & 31;

    if (tid < SS)          s_fi[tid]      = fillers[b * SS + tid];
    else if (tid < 2 * SS) s_ri[tid - SS] = roles[b * SS + (tid - SS)];
    __syncthreads();

    // ---- gather + transpose (conflict-free: bank = 4*l8 + pp + const) ----
    const int l8 = tid & 7;
    const int pp = (tid >> 3) & 3;

    #pragma unroll
    for (int spi = 0; spi < 2; spi++) {
        const int sp = wid * 8 + spi * 4 + pp;   // s-pair 0..63
        const int s  = sp * 2;
        const float* f0 = ftab + (size_t)s_fi[s]     * D1;
        const float* f1 = ftab + (size_t)s_fi[s + 1] * D1;
        #pragma unroll 8
        for (int q = 0; q < 32; q++) {
            const int d = l8 + 8 * q;
            sAw[d * PW1 + sp] = pack_h2(f0[d], f1[d]);
        }
        const float* r0 = rtab + (size_t)s_ri[s]     * D2 + e0;
        const float* r1 = rtab + (size_t)s_ri[s + 1] * D2 + e0;
        #pragma unroll 8
        for (int q = 0; q < 16; q++) {
            const int e = l8 + 8 * q;
            sBw[e * PW1 + sp] = pack_h2(r0[e], r1[e]);
        }
    }
    __syncthreads();

    // ---- MMA phase ----
    const int g  = lane >> 2;
    const int t  = lane & 3;
    const int mw = (wid & 3) * 64;       // d tile
    const int nw = (wid >> 2) * 64;      // e tile (within 128)

    float acc[4][8][4];
    #pragma unroll
    for (int i = 0; i < 4; i++)
        #pragma unroll
        for (int j = 0; j < 8; j++)
            #pragma unroll
            for (int q = 0; q < 4; q++) acc[i][j][q] = 0.f;

    #pragma unroll
    for (int kc = 0; kc < 8; kc++) {
        uint32_t a[4][4];
        #pragma unroll
        for (int i = 0; i < 4; i++) {
            const int base = (mw + 16 * i + g) * PW1 + t + 8 * kc;
            a[i][0] = sAw[base];
            a[i][1] = sAw[base + 8 * PW1];
            a[i][2] = sAw[base + 4];
            a[i][3] = sAw[base + 8 * PW1 + 4];
        }
        uint32_t bf[8][2];
        #pragma unroll
        for (int j = 0; j < 8; j++) {
            const int base = (nw + 8 * j + g) * PW1 + t + 8 * kc;
            bf[j][0] = sBw[base];
            bf[j][1] = sBw[base + 4];
        }
        #pragma unroll
        for (int i = 0; i < 4; i++)
            #pragma unroll
            for (int j = 0; j < 8; j++)
                hmma(acc[i][j], a[i], bf[j]);
    }

    // ---- epilogue: g_tp[b][d][e] fp16 ----
    __half* tpb = g_tp + (size_t)b * KTOT;
    #pragma unroll
    for (int i = 0; i < 4; i++) {
        const int d  = mw + 16 * i + g;
        #pragma unroll
        for (int j = 0; j < 8; j++) {
            const int e = e0 + nw + 8 * j + 2 * t;
            *(uint32_t*)&tpb[(size_t)d * D2 + e] =
                pack_h2(acc[i][j][0], acc[i][j][1]);
            *(uint32_t*)&tpb[(size_t)(d + 8) * D2 + e] =
                pack_h2(acc[i][j][2], acc[i][j][3]);
        }
    }
}

// ---------------------------------------------------------------------------
// Stage 2: fp16 HMMA GEMM. partial[ks][b][o] = sum_{k in split} tp[b,k]*W[o,k]
// grid (8 n-tiles, 16 k-splits), 128 thr (4 warps), warp tile 64m x 32n.
// A fp16 via cp.async (pitch 40 f16, conflict-free); W fp32 in smem (pitch 36),
// converted to f16x2 in the fragment path.
// ---------------------------------------------------------------------------
__global__ __launch_bounds__(128, 1) void gemm2_mma(const float* __restrict__ Wm)
{
    extern __shared__ char dsm[];
    const uint32_t smem_base = smem_u32(dsm);

    const int tid  = threadIdx.x;
    const int wid  = tid >> 5;
    const int lane = tid & 31;
    const int o0   = blockIdx.x * NT2;
    const int ks   = blockIdx.y;
    const size_t k_base = (size_t)ks * KPER2;

    const int g  = lane >> 2;
    const int t  = lane & 3;
    const int n0 = wid * 32;

    // staging maps
    const int c4 = tid & 3,  ra = tid >> 2;   // A: 16B chunk, row 0..31
    const int c8 = tid & 7,  rb = tid >> 3;   // B: 16B chunk, row 0..15

    float acc[4][4][4];
    #pragma unroll
    for (int i = 0; i < 4; i++)
        #pragma unroll
        for (int j = 0; j < 4; j++)
            #pragma unroll
            for (int q = 0; q < 4; q++) acc[i][j][q] = 0.f;

    auto load_stage = [&](int j) {
        if (j < NIT) {
            const uint32_t sb = smem_base + (uint32_t)(j % STG) * STAGE_B;
            const size_t kf = k_base + (size_t)j * KC2;
            #pragma unroll
            for (int p = 0; p < 2; p++) {            // A: tp rows (fp16)
                const int row = ra + 32 * p;
                cp16(sb + (uint32_t)(row * 80 + c4 * 16),
                     g_tp + (size_t)row * KTOT + kf + c4 * 8);
            }
            #pragma unroll
            for (int p = 0; p < 8; p++) {            // B: W rows (fp32)
                const int row = rb + 16 * p;
                cp16(sb + (uint32_t)(A2_BYTES + row * 144 + c8 * 16),
                     Wm + (size_t)(o0 + row) * KTOT + kf + c8 * 4);
            }
        }
        asm volatile("cp.async.commit_group;" ::: "memory");
    };

    #pragma unroll
    for (int j = 0; j < PRE; j++) load_stage(j);

    for (int it = 0; it < NIT; it++) {
        asm volatile("cp.async.wait_group 4;" ::: "memory");
        __syncthreads();

        load_stage(it + PRE);

        const uint32_t* sAw  = (const uint32_t*)(dsm + (it % STG) * STAGE_B);
        const float*    sB32 = (const float*)   (dsm + (it % STG) * STAGE_B + A2_BYTES);

        #pragma unroll
        for (int kc = 0; kc < 2; kc++) {
            uint32_t a[4][4];
            #pragma unroll
            for (int i = 0; i < 4; i++) {
                const int base = (16 * i + g) * 20 + t + 8 * kc;
                a[i][0] = sAw[base];
                a[i][1] = sAw[base + 160];      // +8 rows
                a[i][2] = sAw[base + 4];
                a[i][3] = sAw[base + 164];
            }
            uint32_t bf[4][2];
            #pragma unroll
            for (int j = 0; j < 4; j++) {
                const int fb = (n0 + 8 * j + g) * 36 + 2 * t + 16 * kc;
                bf[j][0] = pack_h2(sB32[fb],     sB32[fb + 1]);
                bf[j][1] = pack_h2(sB32[fb + 8], sB32[fb + 9]);
            }
            #pragma unroll
            for (int i = 0; i < 4; i++)
                #pragma unroll
                for (int j = 0; j < 4; j++)
                    hmma(acc[i][j], a[i], bf[j]);
        }
    }

    float* part = g_partial + (size_t)ks * (BB * ODIM);
    #pragma unroll
    for (int i = 0; i < 4; i++) {
        const int b_row = i * 16 + g;
        #pragma unroll
        for (int j = 0; j < 4; j++) {
            const int col = o0 + n0 + j * 8 + 2 * t;
            *(float2*)(part + (size_t)b_row * ODIM + col) =
                make_float2(acc[i][j][0], acc[i][j][1]);
            *(float2*)(part + (size_t)(b_row + 8) * ODIM + col) =
                make_float2(acc[i][j][2], acc[i][j][3]);
        }
    }
}

// ---------------------------------------------------------------------------
// Reduce: out[b][o] = bias[o] + sum_ks partial[ks][b][o]
// ---------------------------------------------------------------------------
__global__ __launch_bounds__(256) void reduce_kernel(
    const float* __restrict__ bias, float* __restrict__ out)
{
    const int idx = blockIdx.x * blockDim.x + threadIdx.x;
    const int o4  = (idx * 4) & (ODIM - 1);
    const int b   = (idx * 4) >> 10;

    float4 acc = *(const float4*)(bias + o4);
    const float* p = g_partial + (size_t)b * ODIM + o4;
    #pragma unroll
    for (int ks = 0; ks < KS2; ks++) {
        float4 v = *(const float4*)(p + (size_t)ks * (BB * ODIM));
        acc.x += v.x; acc.y += v.y; acc.z += v.z; acc.w += v.w;
    }
    *(float4*)(out + (size_t)b * ODIM + o4) = acc;
}

// ---------------------------------------------------------------------------
extern "C" void kernel_launch(void* const* d_in, const int* in_sizes, int n_in,
                              void* d_out, int out_size)
{
    const int*   fillers = (const int*)  d_in[0];
    const int*   roles   = (const int*)  d_in[1];
    const float* ftab    = (const float*)d_in[2];
    const float* rtab    = (const float*)d_in[3];
    const float* Wm      = (const float*)d_in[4];
    const float* bias    = (const float*)d_in[5];
    float* out = (float*)d_out;

    cudaFuncSetAttribute(tp_mma,    cudaFuncAttributeMaxDynamicSharedMemorySize, SMEM1);
    cudaFuncSetAttribute(gemm2_mma, cudaFuncAttributeMaxDynamicSharedMemorySize, SMEM2);

    tp_mma       <<<dim3(2, BB), 256, SMEM1>>>(fillers, roles, ftab, rtab);
    gemm2_mma    <<<dim3(ODIM / NT2, KS2), 128, SMEM2>>>(Wm);
    reduce_kernel<<<(BB * ODIM / 4) / 256, 256>>>(bias, out);
}

// round 7
// speedup vs baseline: 1.7843x; 1.1454x over previous
#include <cuda_runtime.h>
#include <cuda_fp16.h>
#include <stdint.h>

#define D1    256
#define D2    256
#define ODIM  1024
#define BB    64
#define SS    128
#define KTOT  (D1 * D2)       // 65536

// ---------------- stage-1 (tp) mma config ----------------
#define PW1   68                        // words per smem row (136 f16 = 272 B)
#define SA1_WORDS (128 * PW1)           // A: 128 d rows
#define SB1_WORDS (128 * PW1)           // B: 128 e rows
#define SMEM1 ((SA1_WORDS + SB1_WORDS) * 4)    // 69632 B

// ---------------- stage-2 mma config ----------------
#define KS2   18              // k-split CTAs (8 n-tiles x 18 = 144 CTAs)
#define NT2   128             // n-tile
#define KC2   32              // k per stage
#define STG   6
#define PRE   5
#define TOT_STAGES 2048       // 65536 / 32

#define A2_BYTES  (64 * 80)            // A: 64 rows x (32 f16 + pad)
#define B2_BYTES  (128 * 144)          // B: 128 rows x (32 f32 + pad)
#define STAGE_B   (A2_BYTES + B2_BYTES)
#define SMEM2     (STG * STAGE_B)      // 141312

// Device-global scratch
__device__ __half g_tp[(size_t)BB * KTOT];
__device__ float  g_partial[(size_t)KS2 * BB * ODIM];

// ---------------------------------------------------------------------------
// helpers
// ---------------------------------------------------------------------------
__device__ __forceinline__ uint32_t smem_u32(const void* p) {
    uint32_t a;
    asm("{ .reg .u64 t; cvta.to.shared.u64 t, %1; cvt.u32.u64 %0, t; }" : "=r"(a) : "l"(p));
    return a;
}
__device__ __forceinline__ uint32_t pack_h2(float lo, float hi) {
    uint32_t r;
    asm("cvt.rn.f16x2.f32 %0, %1, %2;" : "=r"(r) : "f"(hi), "f"(lo));
    return r;
}
__device__ __forceinline__ void cp16(uint32_t dst, const void* src) {
    asm volatile("cp.async.cg.shared.global [%0], [%1], 16;" :: "r"(dst), "l"(src));
}
__device__ __forceinline__ void hmma(float* c, const uint32_t* a, const uint32_t* b) {
    asm volatile(
        "mma.sync.aligned.m16n8k16.row.col.f32.f16.f16.f32 "
        "{%0,%1,%2,%3}, {%4,%5,%6,%7}, {%8,%9}, {%0,%1,%2,%3};"
        : "+f"(c[0]), "+f"(c[1]), "+f"(c[2]), "+f"(c[3])
        : "r"(a[0]), "r"(a[1]), "r"(a[2]), "r"(a[3]), "r"(b[0]), "r"(b[1]));
}

// ---------------------------------------------------------------------------
// Stage 1: tp[b, d, e] = sum_s F[fillers[b,s], d] * R[roles[b,s], e]  (fp16 MMA)
// grid (e-half=2, b=64, d-half=2) = 256 CTAs, 128 thr (4 warps), 2 CTAs/SM:
// one CTA's gather overlaps the other's MMA. Warp tile 64d x 64e, k = s = 128.
// ---------------------------------------------------------------------------
__global__ __launch_bounds__(128, 2) void tp_mma(
    const int*   __restrict__ fillers,
    const int*   __restrict__ roles,
    const float* __restrict__ ftab,
    const float* __restrict__ rtab)
{
    extern __shared__ uint32_t sm1[];
    uint32_t* sAw = sm1;                 // [128 d][68] words
    uint32_t* sBw = sm1 + SA1_WORDS;     // [128 e][68] words

    __shared__ int s_fi[SS];
    __shared__ int s_ri[SS];

    const int b   = blockIdx.y;
    const int e0  = blockIdx.x * 128;
    const int d0  = blockIdx.z * 128;
    const int tid = threadIdx.x;
    const int wid  = tid >> 5;
    const int lane = tid & 31;

    s_fi[tid] = fillers[b * SS + tid];
    s_ri[tid] = roles[b * SS + tid];
    __syncthreads();

    // ---- gather + transpose (conflict-free: bank = 4*l8 + sp-offset) ----
    const int l8  = tid & 7;
    const int r16 = tid >> 3;            // 0..15

    #pragma unroll
    for (int spi = 0; spi < 4; spi++) {
        const int sp = r16 + 16 * spi;   // s-pair 0..63
        const int s  = sp * 2;
        const float* f0 = ftab + (size_t)s_fi[s]     * D1 + d0;
        const float* f1 = ftab + (size_t)s_fi[s + 1] * D1 + d0;
        #pragma unroll 8
        for (int q = 0; q < 16; q++) {
            const int d = l8 + 8 * q;
            sAw[d * PW1 + sp] = pack_h2(f0[d], f1[d]);
        }
        const float* r0 = rtab + (size_t)s_ri[s]     * D2 + e0;
        const float* r1 = rtab + (size_t)s_ri[s + 1] * D2 + e0;
        #pragma unroll 8
        for (int q = 0; q < 16; q++) {
            const int e = l8 + 8 * q;
            sBw[e * PW1 + sp] = pack_h2(r0[e], r1[e]);
        }
    }
    __syncthreads();

    // ---- MMA phase: 4 warps, warp tile 64d x 64e ----
    const int g  = lane >> 2;
    const int t  = lane & 3;
    const int mw = (wid & 1) * 64;
    const int nw = (wid >> 1) * 64;

    float acc[4][8][4];
    #pragma unroll
    for (int i = 0; i < 4; i++)
        #pragma unroll
        for (int j = 0; j < 8; j++)
            #pragma unroll
            for (int q = 0; q < 4; q++) acc[i][j][q] = 0.f;

    #pragma unroll
    for (int kc = 0; kc < 8; kc++) {
        uint32_t a[4][4];
        #pragma unroll
        for (int i = 0; i < 4; i++) {
            const int base = (mw + 16 * i + g) * PW1 + t + 8 * kc;
            a[i][0] = sAw[base];
            a[i][1] = sAw[base + 8 * PW1];
            a[i][2] = sAw[base + 4];
            a[i][3] = sAw[base + 8 * PW1 + 4];
        }
        uint32_t bf[8][2];
        #pragma unroll
        for (int j = 0; j < 8; j++) {
            const int base = (nw + 8 * j + g) * PW1 + t + 8 * kc;
            bf[j][0] = sBw[base];
            bf[j][1] = sBw[base + 4];
        }
        #pragma unroll
        for (int i = 0; i < 4; i++)
            #pragma unroll
            for (int j = 0; j < 8; j++)
                hmma(acc[i][j], a[i], bf[j]);
    }

    // ---- epilogue: g_tp[b][d][e] fp16 ----
    __half* tpb = g_tp + (size_t)b * KTOT;
    #pragma unroll
    for (int i = 0; i < 4; i++) {
        const int d = d0 + mw + 16 * i + g;
        #pragma unroll
        for (int j = 0; j < 8; j++) {
            const int e = e0 + nw + 8 * j + 2 * t;
            *(uint32_t*)&tpb[(size_t)d * D2 + e] =
                pack_h2(acc[i][j][0], acc[i][j][1]);
            *(uint32_t*)&tpb[(size_t)(d + 8) * D2 + e] =
                pack_h2(acc[i][j][2], acc[i][j][3]);
        }
    }
}

// ---------------------------------------------------------------------------
// Stage 2: fp16 HMMA GEMM. partial[ks][b][o] = sum_{k in split ks} tp[b,k]*W[o,k]
// grid (8 n-tiles, 18 k-splits) = 144 CTAs (1/SM). 128 thr (4 warps),
// warp tile 64m x 32n. Uneven split: ks<14 -> 114 stages, else 113.
// ---------------------------------------------------------------------------
__global__ __launch_bounds__(128, 1) void gemm2_mma(const float* __restrict__ Wm)
{
    extern __shared__ char dsm[];
    const uint32_t smem_base = smem_u32(dsm);

    const int tid  = threadIdx.x;
    const int wid  = tid >> 5;
    const int lane = tid & 31;
    const int o0   = blockIdx.x * NT2;
    const int ks   = blockIdx.y;

    const int nstages = 113 + (ks < 14 ? 1 : 0);
    const size_t k_base = ((size_t)ks * 113 + (ks < 14 ? ks : 14)) * KC2;

    const int g  = lane >> 2;
    const int t  = lane & 3;
    const int n0 = wid * 32;

    const int c4 = tid & 3,  ra = tid >> 2;   // A staging
    const int c8 = tid & 7,  rb = tid >> 3;   // B staging

    float acc[4][4][4];
    #pragma unroll
    for (int i = 0; i < 4; i++)
        #pragma unroll
        for (int j = 0; j < 4; j++)
            #pragma unroll
            for (int q = 0; q < 4; q++) acc[i][j][q] = 0.f;

    auto load_stage = [&](int j) {
        if (j < nstages) {
            const uint32_t sb = smem_base + (uint32_t)(j % STG) * STAGE_B;
            const size_t kf = k_base + (size_t)j * KC2;
            #pragma unroll
            for (int p = 0; p < 2; p++) {            // A: tp rows (fp16)
                const int row = ra + 32 * p;
                cp16(sb + (uint32_t)(row * 80 + c4 * 16),
                     g_tp + (size_t)row * KTOT + kf + c4 * 8);
            }
            #pragma unroll
            for (int p = 0; p < 8; p++) {            // B: W rows (fp32)
                const int row = rb + 16 * p;
                cp16(sb + (uint32_t)(A2_BYTES + row * 144 + c8 * 16),
                     Wm + (size_t)(o0 + row) * KTOT + kf + c8 * 4);
            }
        }
        asm volatile("cp.async.commit_group;" ::: "memory");
    };

    #pragma unroll
    for (int j = 0; j < PRE; j++) load_stage(j);

    for (int it = 0; it < nstages; it++) {
        asm volatile("cp.async.wait_group 4;" ::: "memory");
        __syncthreads();

        load_stage(it + PRE);

        const uint32_t* sAw  = (const uint32_t*)(dsm + (it % STG) * STAGE_B);
        const float*    sB32 = (const float*)   (dsm + (it % STG) * STAGE_B + A2_BYTES);

        #pragma unroll
        for (int kc = 0; kc < 2; kc++) {
            uint32_t a[4][4];
            #pragma unroll
            for (int i = 0; i < 4; i++) {
                const int base = (16 * i + g) * 20 + t + 8 * kc;
                a[i][0] = sAw[base];
                a[i][1] = sAw[base + 160];
                a[i][2] = sAw[base + 4];
                a[i][3] = sAw[base + 164];
            }
            uint32_t bf[4][2];
            #pragma unroll
            for (int j = 0; j < 4; j++) {
                const int fb = (n0 + 8 * j + g) * 36 + 2 * t + 16 * kc;
                bf[j][0] = pack_h2(sB32[fb],     sB32[fb + 1]);
                bf[j][1] = pack_h2(sB32[fb + 8], sB32[fb + 9]);
            }
            #pragma unroll
            for (int i = 0; i < 4; i++)
                #pragma unroll
                for (int j = 0; j < 4; j++)
                    hmma(acc[i][j], a[i], bf[j]);
        }
    }

    float* part = g_partial + (size_t)ks * (BB * ODIM);
    #pragma unroll
    for (int i = 0; i < 4; i++) {
        const int b_row = i * 16 + g;
        #pragma unroll
        for (int j = 0; j < 4; j++) {
            const int col = o0 + n0 + j * 8 + 2 * t;
            *(float2*)(part + (size_t)b_row * ODIM + col) =
                make_float2(acc[i][j][0], acc[i][j][1]);
            *(float2*)(part + (size_t)(b_row + 8) * ODIM + col) =
                make_float2(acc[i][j][2], acc[i][j][3]);
        }
    }
}

// ---------------------------------------------------------------------------
// Reduce: out[b][o] = bias[o] + sum_ks partial[ks][b][o]
// ---------------------------------------------------------------------------
__global__ __launch_bounds__(256) void reduce_kernel(
    const float* __restrict__ bias, float* __restrict__ out)
{
    const int idx = blockIdx.x * blockDim.x + threadIdx.x;
    const int o4  = (idx * 4) & (ODIM - 1);
    const int b   = (idx * 4) >> 10;

    float4 acc = *(const float4*)(bias + o4);
    const float* p = g_partial + (size_t)b * ODIM + o4;
    #pragma unroll
    for (int ks = 0; ks < KS2; ks++) {
        float4 v = *(const float4*)(p + (size_t)ks * (BB * ODIM));
        acc.x += v.x; acc.y += v.y; acc.z += v.z; acc.w += v.w;
    }
    *(float4*)(out + (size_t)b * ODIM + o4) = acc;
}

// ---------------------------------------------------------------------------
extern "C" void kernel_launch(void* const* d_in, const int* in_sizes, int n_in,
                              void* d_out, int out_size)
{
    const int*   fillers = (const int*)  d_in[0];
    const int*   roles   = (const int*)  d_in[1];
    const float* ftab    = (const float*)d_in[2];
    const float* rtab    = (const float*)d_in[3];
    const float* Wm      = (const float*)d_in[4];
    const float* bias    = (const float*)d_in[5];
    float* out = (float*)d_out;

    cudaFuncSetAttribute(tp_mma,    cudaFuncAttributeMaxDynamicSharedMemorySize, SMEM1);
    cudaFuncSetAttribute(gemm2_mma, cudaFuncAttributeMaxDynamicSharedMemorySize, SMEM2);

    tp_mma       <<<dim3(2, BB, 2), 128, SMEM1>>>(fillers, roles, ftab, rtab);
    gemm2_mma    <<<dim3(ODIM / NT2, KS2), 128, SMEM2>>>(Wm);
    reduce_kernel<<<(BB * ODIM / 4) / 256, 256>>>(bias, out);
}

// round 8
// speedup vs baseline: 1.8828x; 1.0552x over previous
#include <cuda_runtime.h>
#include <cuda_fp16.h>
#include <stdint.h>

#define D1    256
#define D2    256
#define ODIM  1024
#define BB    64
#define SS    128
#define KTOT  (D1 * D2)       // 65536

// ---------------- stage-1 (tp) config ----------------
#define NCH   4               // s-chunks
#define CHS   32              // s per chunk
#define PF    260             // F smem pitch (floats): 2t*260 mod 32 = 8t -> conflict-free
#define PR    132             // R smem pitch (floats)
#define F_STAGE_W (CHS * PF)  // 8320
#define R_STAGE_W (CHS * PR)  // 4224
#define STAGE1_W  (F_STAGE_W + R_STAGE_W)
#define SMEM1     (2 * STAGE1_W * 4)   // 100352 B

// ---------------- stage-2 mma config ----------------
#define KS2   18
#define NT2   128
#define KC2   32
#define STG   6
#define PRE   5

#define A2_BYTES  (64 * 80)
#define B2_BYTES  (128 * 144)
#define STAGE_B   (A2_BYTES + B2_BYTES)
#define SMEM2     (STG * STAGE_B)

// Device-global scratch
__device__ __half g_tp[(size_t)BB * KTOT];
__device__ float  g_partial[(size_t)KS2 * BB * ODIM];

// ---------------------------------------------------------------------------
// helpers
// ---------------------------------------------------------------------------
__device__ __forceinline__ uint32_t smem_u32(const void* p) {
    uint32_t a;
    asm("{ .reg .u64 t; cvta.to.shared.u64 t, %1; cvt.u32.u64 %0, t; }" : "=r"(a) : "l"(p));
    return a;
}
__device__ __forceinline__ uint32_t pack_h2(float lo, float hi) {
    uint32_t r;
    asm("cvt.rn.f16x2.f32 %0, %1, %2;" : "=r"(r) : "f"(hi), "f"(lo));
    return r;
}
__device__ __forceinline__ void cp16(uint32_t dst, const void* src) {
    asm volatile("cp.async.cg.shared.global [%0], [%1], 16;" :: "r"(dst), "l"(src));
}
__device__ __forceinline__ void hmma(float* c, const uint32_t* a, const uint32_t* b) {
    asm volatile(
        "mma.sync.aligned.m16n8k16.row.col.f32.f16.f16.f32 "
        "{%0,%1,%2,%3}, {%4,%5,%6,%7}, {%8,%9}, {%0,%1,%2,%3};"
        : "+f"(c[0]), "+f"(c[1]), "+f"(c[2]), "+f"(c[3])
        : "r"(a[0]), "r"(a[1]), "r"(a[2]), "r"(a[3]), "r"(b[0]), "r"(b[1]));
}

// ---------------------------------------------------------------------------
// Stage 1: tp[b, d, e] = sum_s F[fillers[b,s], d] * R[roles[b,s], e]
// grid (e-half=2, b=64) = 128 CTAs, 256 thr (8 warps, warp tile 64d x 64e).
// Gather: cp.async of raw fp32 rows into [s][d]/[s][e] smem (double-buffered,
// 4 s-chunks of 32); fp32->fp16 conversion happens in the fragment path.
// ---------------------------------------------------------------------------
__global__ __launch_bounds__(256, 1) void tp_mma(
    const int*   __restrict__ fillers,
    const int*   __restrict__ roles,
    const float* __restrict__ ftab,
    const float* __restrict__ rtab)
{
    extern __shared__ float sm1[];
    __shared__ int s_fi[SS];
    __shared__ int s_ri[SS];

    const int b   = blockIdx.y;
    const int e0  = blockIdx.x * 128;
    const int tid = threadIdx.x;
    const int wid  = tid >> 5;
    const int lane = tid & 31;

    if (tid < SS)          s_fi[tid]      = fillers[b * SS + tid];
    else                   s_ri[tid - SS] = roles[b * SS + (tid - SS)];
    __syncthreads();

    // staging: thread -> (row rw 0..31, 16B chunk c8 0..7)
    const int c8 = tid & 7;
    const int rw = tid >> 3;

    auto load_chunk = [&](int ch) {
        if (ch < NCH) {
            float* dstF = sm1 + (ch & 1) * STAGE1_W;
            float* dstR = dstF + F_STAGE_W;
            const int s = ch * CHS + rw;
            const float* fr = ftab + (size_t)s_fi[s] * D1;
            const uint32_t dF = smem_u32(dstF + rw * PF) + c8 * 16;
            #pragma unroll
            for (int q = 0; q < 8; q++)
                cp16(dF + q * 128, fr + c8 * 4 + q * 32);     // 1 KB row
            const float* rr = rtab + (size_t)s_ri[s] * D2 + e0;
            const uint32_t dR = smem_u32(dstR + rw * PR) + c8 * 16;
            #pragma unroll
            for (int q = 0; q < 4; q++)
                cp16(dR + q * 128, rr + c8 * 4 + q * 32);     // 512 B row
        }
        asm volatile("cp.async.commit_group;" ::: "memory");
    };

    // MMA mapping: 8 warps = 4 d-tiles x 2 e-tiles
    const int g  = lane >> 2;
    const int t  = lane & 3;
    const int mw = (wid & 3) * 64;
    const int nw = (wid >> 2) * 64;

    float acc[4][8][4];
    #pragma unroll
    for (int i = 0; i < 4; i++)
        #pragma unroll
        for (int j = 0; j < 8; j++)
            #pragma unroll
            for (int q = 0; q < 4; q++) acc[i][j][q] = 0.f;

    load_chunk(0);

    for (int ch = 0; ch < NCH; ch++) {
        load_chunk(ch + 1);
        asm volatile("cp.async.wait_group 1;" ::: "memory");
        __syncthreads();

        const float* sF = sm1 + (ch & 1) * STAGE1_W;
        const float* sR = sF + F_STAGE_W;

        #pragma unroll
        for (int kc = 0; kc < 2; kc++) {
            const int k0 = kc * 16;
            uint32_t a[4][4];
            #pragma unroll
            for (int i = 0; i < 4; i++) {
                const int m = mw + 16 * i + g;
                const float* p0 = sF + (k0 + 2 * t)     * PF;
                const float* p1 = sF + (k0 + 2 * t + 1) * PF;
                const float* p2 = sF + (k0 + 2 * t + 8) * PF;
                const float* p3 = sF + (k0 + 2 * t + 9) * PF;
                a[i][0] = pack_h2(p0[m],     p1[m]);
                a[i][1] = pack_h2(p0[m + 8], p1[m + 8]);
                a[i][2] = pack_h2(p2[m],     p3[m]);
                a[i][3] = pack_h2(p2[m + 8], p3[m + 8]);
            }
            uint32_t bw[8][2];
            #pragma unroll
            for (int j = 0; j < 8; j++) {
                const int n = nw + 8 * j + g;
                const float* q0 = sR + (k0 + 2 * t)     * PR;
                const float* q1 = sR + (k0 + 2 * t + 1) * PR;
                const float* q2 = sR + (k0 + 2 * t + 8) * PR;
                const float* q3 = sR + (k0 + 2 * t + 9) * PR;
                bw[j][0] = pack_h2(q0[n], q1[n]);
                bw[j][1] = pack_h2(q2[n], q3[n]);
            }
            #pragma unroll
            for (int i = 0; i < 4; i++)
                #pragma unroll
                for (int j = 0; j < 8; j++)
                    hmma(acc[i][j], a[i], bw[j]);
        }
        __syncthreads();
    }

    // epilogue: g_tp[b][d][e] fp16
    __half* tpb = g_tp + (size_t)b * KTOT;
    #pragma unroll
    for (int i = 0; i < 4; i++) {
        const int d = mw + 16 * i + g;
        #pragma unroll
        for (int j = 0; j < 8; j++) {
            const int e = e0 + nw + 8 * j + 2 * t;
            *(uint32_t*)&tpb[(size_t)d * D2 + e] =
                pack_h2(acc[i][j][0], acc[i][j][1]);
            *(uint32_t*)&tpb[(size_t)(d + 8) * D2 + e] =
                pack_h2(acc[i][j][2], acc[i][j][3]);
        }
    }
}

// ---------------------------------------------------------------------------
// Stage 2: fp16 HMMA GEMM (at legacy-pipe floor). 8 n-tiles x 18 k-splits.
// ---------------------------------------------------------------------------
__global__ __launch_bounds__(128, 1) void gemm2_mma(const float* __restrict__ Wm)
{
    extern __shared__ char dsm[];
    const uint32_t smem_base = smem_u32(dsm);

    const int tid  = threadIdx.x;
    const int wid  = tid >> 5;
    const int lane = tid & 31;
    const int o0   = blockIdx.x * NT2;
    const int ks   = blockIdx.y;

    const int nstages = 113 + (ks < 14 ? 1 : 0);
    const size_t k_base = ((size_t)ks * 113 + (ks < 14 ? ks : 14)) * KC2;

    const int g  = lane >> 2;
    const int t  = lane & 3;
    const int n0 = wid * 32;

    const int c4 = tid & 3,  ra = tid >> 2;
    const int c8 = tid & 7,  rb = tid >> 3;

    float acc[4][4][4];
    #pragma unroll
    for (int i = 0; i < 4; i++)
        #pragma unroll
        for (int j = 0; j < 4; j++)
            #pragma unroll
            for (int q = 0; q < 4; q++) acc[i][j][q] = 0.f;

    auto load_stage = [&](int j) {
        if (j < nstages) {
            const uint32_t sb = smem_base + (uint32_t)(j % STG) * STAGE_B;
            const size_t kf = k_base + (size_t)j * KC2;
            #pragma unroll
            for (int p = 0; p < 2; p++) {
                const int row = ra + 32 * p;
                cp16(sb + (uint32_t)(row * 80 + c4 * 16),
                     g_tp + (size_t)row * KTOT + kf + c4 * 8);
            }
            #pragma unroll
            for (int p = 0; p < 8; p++) {
                const int row = rb + 16 * p;
                cp16(sb + (uint32_t)(A2_BYTES + row * 144 + c8 * 16),
                     Wm + (size_t)(o0 + row) * KTOT + kf + c8 * 4);
            }
        }
        asm volatile("cp.async.commit_group;" ::: "memory");
    };

    #pragma unroll
    for (int j = 0; j < PRE; j++) load_stage(j);

    for (int it = 0; it < nstages; it++) {
        asm volatile("cp.async.wait_group 4;" ::: "memory");
        __syncthreads();

        load_stage(it + PRE);

        const uint32_t* sAw  = (const uint32_t*)(dsm + (it % STG) * STAGE_B);
        const float*    sB32 = (const float*)   (dsm + (it % STG) * STAGE_B + A2_BYTES);

        #pragma unroll
        for (int kc = 0; kc < 2; kc++) {
            uint32_t a[4][4];
            #pragma unroll
            for (int i = 0; i < 4; i++) {
                const int base = (16 * i + g) * 20 + t + 8 * kc;
                a[i][0] = sAw[base];
                a[i][1] = sAw[base + 160];
                a[i][2] = sAw[base + 4];
                a[i][3] = sAw[base + 164];
            }
            uint32_t bf[4][2];
            #pragma unroll
            for (int j = 0; j < 4; j++) {
                const int fb = (n0 + 8 * j + g) * 36 + 2 * t + 16 * kc;
                bf[j][0] = pack_h2(sB32[fb],     sB32[fb + 1]);
                bf[j][1] = pack_h2(sB32[fb + 8], sB32[fb + 9]);
            }
            #pragma unroll
            for (int i = 0; i < 4; i++)
                #pragma unroll
                for (int j = 0; j < 4; j++)
                    hmma(acc[i][j], a[i], bf[j]);
        }
    }

    float* part = g_partial + (size_t)ks * (BB * ODIM);
    #pragma unroll
    for (int i = 0; i < 4; i++) {
        const int b_row = i * 16 + g;
        #pragma unroll
        for (int j = 0; j < 4; j++) {
            const int col = o0 + n0 + j * 8 + 2 * t;
            *(float2*)(part + (size_t)b_row * ODIM + col) =
                make_float2(acc[i][j][0], acc[i][j][1]);
            *(float2*)(part + (size_t)(b_row + 8) * ODIM + col) =
                make_float2(acc[i][j][2], acc[i][j][3]);
        }
    }
}

// ---------------------------------------------------------------------------
// Reduce: out[b][o] = bias[o] + sum_ks partial[ks][b][o]
// ---------------------------------------------------------------------------
__global__ __launch_bounds__(256) void reduce_kernel(
    const float* __restrict__ bias, float* __restrict__ out)
{
    const int idx = blockIdx.x * blockDim.x + threadIdx.x;
    const int o4  = (idx * 4) & (ODIM - 1);
    const int b   = (idx * 4) >> 10;

    float4 acc = *(const float4*)(bias + o4);
    const float* p = g_partial + (size_t)b * ODIM + o4;
    #pragma unroll
    for (int ks = 0; ks < KS2; ks++) {
        float4 v = *(const float4*)(p + (size_t)ks * (BB * ODIM));
        acc.x += v.x; acc.y += v.y; acc.z += v.z; acc.w += v.w;
    }
    *(float4*)(out + (size_t)b * ODIM + o4) = acc;
}

// ---------------------------------------------------------------------------
extern "C" void kernel_launch(void* const* d_in, const int* in_sizes, int n_in,
                              void* d_out, int out_size)
{
    const int*   fillers = (const int*)  d_in[0];
    const int*   roles   = (const int*)  d_in[1];
    const float* ftab    = (const float*)d_in[2];
    const float* rtab    = (const float*)d_in[3];
    const float* Wm      = (const float*)d_in[4];
    const float* bias    = (const float*)d_in[5];
    float* out = (float*)d_out;

    cudaFuncSetAttribute(tp_mma,    cudaFuncAttributeMaxDynamicSharedMemorySize, SMEM1);
    cudaFuncSetAttribute(gemm2_mma, cudaFuncAttributeMaxDynamicSharedMemorySize, SMEM2);

    tp_mma       <<<dim3(2, BB), 256, SMEM1>>>(fillers, roles, ftab, rtab);
    gemm2_mma    <<<dim3(ODIM / NT2, KS2), 128, SMEM2>>>(Wm);
    reduce_kernel<<<(BB * ODIM / 4) / 256, 256>>>(bias, out);
}